// round 1
// baseline (speedup 1.0000x reference)
#include <cuda_runtime.h>
#include <math.h>

#define Bb 4
#define Ss 2048
#define Ee 1024
#define Hh 16
#define Dd 64
#define M1 (Bb*Ss)     // 8192
#define PITCH 65       // shared-mem row pitch (floats) to dodge bank conflicts

// Scratch (allocation-free: device globals)
__device__ float g_q[(size_t)Bb*Hh*Ss*Dd];   // [B,H,S,D]
__device__ float g_k[(size_t)Bb*Hh*Ss*Dd];
__device__ float g_v[(size_t)Bb*Hh*Ss*Dd];
__device__ float g_ao[(size_t)Bb*Ss*Ee];     // attention output [B,S,E]

// ---------------------------------------------------------------------------
// SGEMM: C = A[M,K] @ W[K,N] + bias
// MODE 0: epilogue scatters into g_q/g_k/g_v ([B,H,S,D] layout), A = x
// MODE 1: A = g_ao (internal), C = d_out plain row-major
// 128x128 block, BK=8, 256 threads, 8x8 per-thread micro-tile.
// ---------------------------------------------------------------------------
template<int MODE>
__global__ void __launch_bounds__(256)
sgemm_kernel(const float* __restrict__ A_in,
             const float* __restrict__ W,
             const float* __restrict__ bias,
             float* __restrict__ C,
             int M, int N, int K)
{
    const int BM = 128, BN = 128, BK = 8;
    __shared__ float As[BK][BM];
    __shared__ float Bs[BK][BN];

    const float* A = (MODE == 1) ? g_ao : A_in;

    const int tid  = threadIdx.x;
    const int brow = blockIdx.y * BM;
    const int bcol = blockIdx.x * BN;
    const int arow = tid >> 1;          // 0..127
    const int acol = (tid & 1) * 4;     // 0 or 4
    const int brw  = tid >> 5;          // 0..7
    const int bcl  = (tid & 31) * 4;    // 0..124
    const int ty   = tid >> 4;          // 0..15
    const int tx   = tid & 15;          // 0..15

    float acc[8][8];
    #pragma unroll
    for (int i = 0; i < 8; i++)
        #pragma unroll
        for (int j = 0; j < 8; j++) acc[i][j] = 0.f;

    for (int k0 = 0; k0 < K; k0 += BK) {
        float4 av = *(const float4*)(A + (size_t)(brow + arow) * K + k0 + acol);
        As[acol + 0][arow] = av.x;
        As[acol + 1][arow] = av.y;
        As[acol + 2][arow] = av.z;
        As[acol + 3][arow] = av.w;
        float4 bv = *(const float4*)(W + (size_t)(k0 + brw) * N + bcol + bcl);
        *(float4*)&Bs[brw][bcl] = bv;
        __syncthreads();

        #pragma unroll
        for (int kk = 0; kk < BK; kk++) {
            float a[8], b[8];
            *(float4*)&a[0] = *(const float4*)&As[kk][ty * 8];
            *(float4*)&a[4] = *(const float4*)&As[kk][ty * 8 + 4];
            *(float4*)&b[0] = *(const float4*)&Bs[kk][tx * 8];
            *(float4*)&b[4] = *(const float4*)&Bs[kk][tx * 8 + 4];
            #pragma unroll
            for (int i = 0; i < 8; i++)
                #pragma unroll
                for (int j = 0; j < 8; j++)
                    acc[i][j] += a[i] * b[j];
        }
        __syncthreads();
    }

    #pragma unroll
    for (int i = 0; i < 8; i++) {
        const int m = brow + ty * 8 + i;
        #pragma unroll
        for (int j = 0; j < 8; j++) {
            const int n = bcol + tx * 8 + j;
            const float v = acc[i][j] + bias[n];
            if (MODE == 0) {
                // n in [0,3E): which matrix, then [B,H,S,D] scatter
                const int which = n >> 10;          // 0=q,1=k,2=v (E=1024)
                const int e = n & (Ee - 1);
                const int h = e >> 6;               // D=64
                const int d = e & (Dd - 1);
                const int b = m >> 11;              // S=2048
                const int s = m & (Ss - 1);
                const size_t idx = (((size_t)(b * Hh + h)) * Ss + s) * Dd + d;
                float* dst = (which == 0) ? g_q : ((which == 1) ? g_k : g_v);
                dst[idx] = v;
            } else {
                C[(size_t)m * N + n] = v;
            }
        }
    }
}

// ---------------------------------------------------------------------------
// Flash attention, fp32. One block per (q-tile of 64 rows, head, batch).
// 256 threads as 16x16; each thread owns a 4x4 patch of the 64x64 score tile
// and a 4x4 patch of the 64-wide output accumulator. Online softmax with
// shuffle reductions across the 16 threads sharing a row. Causal tile skip.
// ---------------------------------------------------------------------------
__global__ void __launch_bounds__(256)
flash_attn_kernel(const int* __restrict__ amask)
{
    const int qt = blockIdx.x;           // 0..31 (S/64)
    const int h  = blockIdx.y;
    const int b  = blockIdx.z;

    extern __shared__ float sh[];
    float* Qs = sh;                      // [64][PITCH]
    float* Ks = Qs + 64 * PITCH;
    float* Vs = Ks + 64 * PITCH;
    float* Ps = Vs + 64 * PITCH;
    __shared__ int mk[64];

    const int tid = threadIdx.x;
    const int ty  = tid >> 4;            // row group 0..15
    const int tx  = tid & 15;            // col group 0..15
    const float scale = 0.125f;          // 1/sqrt(64)

    const float* qptr = g_q + (((size_t)(b * Hh + h)) * Ss + qt * 64) * Dd;
    const float* kbase = g_k + ((size_t)(b * Hh + h)) * Ss * Dd;
    const float* vbase = g_v + ((size_t)(b * Hh + h)) * Ss * Dd;

    // Load Q tile: 64x64, 1024 float4 total
    for (int t = tid; t < 64 * 16; t += 256) {
        const int r  = t >> 4;
        const int c4 = (t & 15) * 4;
        float4 v = *(const float4*)(qptr + r * 64 + c4);
        Qs[r * PITCH + c4 + 0] = v.x;
        Qs[r * PITCH + c4 + 1] = v.y;
        Qs[r * PITCH + c4 + 2] = v.z;
        Qs[r * PITCH + c4 + 3] = v.w;
    }

    float m_i[4], l_i[4], o[4][4];
    #pragma unroll
    for (int i = 0; i < 4; i++) {
        m_i[i] = -INFINITY; l_i[i] = 0.f;
        #pragma unroll
        for (int j = 0; j < 4; j++) o[i][j] = 0.f;
    }

    for (int jt = 0; jt <= qt; jt++) {
        __syncthreads();   // previous iteration's shared reads done (also covers Q load)
        for (int t = tid; t < 64 * 16; t += 256) {
            const int r  = t >> 4;
            const int c4 = (t & 15) * 4;
            float4 kv = *(const float4*)(kbase + (size_t)(jt * 64 + r) * 64 + c4);
            Ks[r * PITCH + c4 + 0] = kv.x; Ks[r * PITCH + c4 + 1] = kv.y;
            Ks[r * PITCH + c4 + 2] = kv.z; Ks[r * PITCH + c4 + 3] = kv.w;
            float4 vv = *(const float4*)(vbase + (size_t)(jt * 64 + r) * 64 + c4);
            Vs[r * PITCH + c4 + 0] = vv.x; Vs[r * PITCH + c4 + 1] = vv.y;
            Vs[r * PITCH + c4 + 2] = vv.z; Vs[r * PITCH + c4 + 3] = vv.w;
        }
        if (tid < 64) mk[tid] = amask[b * Ss + jt * 64 + tid];
        __syncthreads();

        // S = Q K^T
        float s[4][4];
        #pragma unroll
        for (int i = 0; i < 4; i++)
            #pragma unroll
            for (int j = 0; j < 4; j++) s[i][j] = 0.f;

        #pragma unroll 8
        for (int d = 0; d < 64; d++) {
            float qv[4], kv[4];
            #pragma unroll
            for (int i = 0; i < 4; i++) qv[i] = Qs[(ty * 4 + i) * PITCH + d];
            #pragma unroll
            for (int j = 0; j < 4; j++) kv[j] = Ks[(tx * 4 + j) * PITCH + d];
            #pragma unroll
            for (int i = 0; i < 4; i++)
                #pragma unroll
                for (int j = 0; j < 4; j++)
                    s[i][j] += qv[i] * kv[j];
        }

        // masking (causal only needed on the diagonal tile) + padding mask
        const bool diag = (jt == qt);
        #pragma unroll
        for (int i = 0; i < 4; i++) {
            const int r = ty * 4 + i;
            #pragma unroll
            for (int j = 0; j < 4; j++) {
                const int c = tx * 4 + j;
                const bool ok = (mk[c] != 0) && (!diag || c <= r);
                s[i][j] = ok ? s[i][j] * scale : -INFINITY;
            }
        }

        // online softmax (row reductions across the 16 tx lanes; xor<16 stays
        // inside the 16-lane group since tx == lane%16)
        #pragma unroll
        for (int i = 0; i < 4; i++) {
            float mx = fmaxf(fmaxf(s[i][0], s[i][1]), fmaxf(s[i][2], s[i][3]));
            #pragma unroll
            for (int off = 1; off < 16; off <<= 1)
                mx = fmaxf(mx, __shfl_xor_sync(0xffffffffu, mx, off));
            const float mnew  = fmaxf(m_i[i], mx);
            const float alpha = __expf(m_i[i] - mnew);
            float rsum = 0.f;
            #pragma unroll
            for (int j = 0; j < 4; j++) {
                s[i][j] = __expf(s[i][j] - mnew);
                rsum += s[i][j];
            }
            #pragma unroll
            for (int off = 1; off < 16; off <<= 1)
                rsum += __shfl_xor_sync(0xffffffffu, rsum, off);
            l_i[i] = l_i[i] * alpha + rsum;
            m_i[i] = mnew;
            #pragma unroll
            for (int j = 0; j < 4; j++) o[i][j] *= alpha;
        }

        // stage P and accumulate O += P @ V
        #pragma unroll
        for (int i = 0; i < 4; i++)
            #pragma unroll
            for (int j = 0; j < 4; j++)
                Ps[(ty * 4 + i) * PITCH + tx * 4 + j] = s[i][j];
        __syncthreads();

        #pragma unroll 8
        for (int k = 0; k < 64; k++) {
            float pv[4], vv[4];
            #pragma unroll
            for (int i = 0; i < 4; i++) pv[i] = Ps[(ty * 4 + i) * PITCH + k];
            #pragma unroll
            for (int j = 0; j < 4; j++) vv[j] = Vs[k * PITCH + tx * 4 + j];
            #pragma unroll
            for (int i = 0; i < 4; i++)
                #pragma unroll
                for (int j = 0; j < 4; j++)
                    o[i][j] += pv[i] * vv[j];
        }
    }

    // write to g_ao as [B,S,E] with column offset h*D
    #pragma unroll
    for (int i = 0; i < 4; i++) {
        const int r = ty * 4 + i;
        const float inv = 1.f / l_i[i];
        const size_t rowoff = ((size_t)b * Ss + qt * 64 + r) * Ee + h * Dd;
        #pragma unroll
        for (int j = 0; j < 4; j++)
            g_ao[rowoff + tx * 4 + j] = o[i][j] * inv;
    }
}

// ---------------------------------------------------------------------------
extern "C" void kernel_launch(void* const* d_in, const int* in_sizes, int n_in,
                              void* d_out, int out_size)
{
    const float* x     = (const float*)d_in[0];
    const int*   amask = (const int*)  d_in[1];
    const float* Wqkv  = (const float*)d_in[2];
    const float* bqkv  = (const float*)d_in[3];
    const float* Wproj = (const float*)d_in[4];
    const float* bproj = (const float*)d_in[5];
    float* out = (float*)d_out;

    // 1) QKV GEMM: [8192,1024] @ [1024,3072] + b, scatter into [B,H,S,D]
    {
        dim3 grid(3 * Ee / 128, M1 / 128);   // 24 x 64
        sgemm_kernel<0><<<grid, 256>>>(x, Wqkv, bqkv, nullptr, M1, 3 * Ee, Ee);
    }

    // 2) Flash attention
    {
        const size_t shbytes = (size_t)4 * 64 * PITCH * sizeof(float);  // ~66.6 KB
        cudaFuncSetAttribute(flash_attn_kernel,
                             cudaFuncAttributeMaxDynamicSharedMemorySize,
                             (int)shbytes);
        dim3 grid(Ss / 64, Hh, Bb);          // 32 x 16 x 4
        flash_attn_kernel<<<grid, 256, shbytes>>>(amask);
    }

    // 3) Projection GEMM: g_ao [8192,1024] @ [1024,1024] + b -> out
    {
        dim3 grid(Ee / 128, M1 / 128);       // 8 x 64
        sgemm_kernel<1><<<grid, 256>>>(nullptr, Wproj, bproj, out, M1, Ee, Ee);
    }
}

// round 2
// speedup vs baseline: 1.8348x; 1.8348x over previous
#include <cuda_runtime.h>
#include <math.h>
#include <stdint.h>

#define Bb 4
#define Ss 2048
#define Ee 1024
#define Hh 16
#define Dd 64
#define M1 (Bb*Ss)     // 8192
#define PITCH 65       // flash kernel smem pitch

// Scratch (allocation-free: device globals)
__device__ float g_q[(size_t)Bb*Hh*Ss*Dd];   // [B,H,S,D]
__device__ float g_k[(size_t)Bb*Hh*Ss*Dd];
__device__ float g_v[(size_t)Bb*Hh*Ss*Dd];
__device__ float g_ao[(size_t)Bb*Ss*Ee];     // attention output [B,S,E]

__device__ __forceinline__ float f2tf32(float x) {
    uint32_t u;
    asm("cvt.rna.tf32.f32 %0, %1;" : "=r"(u) : "f"(x));
    return __uint_as_float(u);
}

__device__ __forceinline__ void mma_tf32(float* d, const float* a, const float* b) {
    asm volatile(
        "mma.sync.aligned.m16n8k8.row.col.f32.tf32.tf32.f32 "
        "{%0,%1,%2,%3}, {%4,%5,%6,%7}, {%8,%9}, {%0,%1,%2,%3};"
        : "+f"(d[0]), "+f"(d[1]), "+f"(d[2]), "+f"(d[3])
        : "r"(__float_as_uint(a[0])), "r"(__float_as_uint(a[1])),
          "r"(__float_as_uint(a[2])), "r"(__float_as_uint(a[3])),
          "r"(__float_as_uint(b[0])), "r"(__float_as_uint(b[1])));
}

// ---------------------------------------------------------------------------
// TF32 tensor-core GEMM: C = A[M,K] @ W[K,N] + bias
// MODE 0: epilogue scatters into g_q/g_k/g_v ([B,H,S,D] layout), A = x
// MODE 1: A = g_ao (internal), C = d_out plain row-major
// 128x128 block, BK=32, 256 threads (8 warps, 2x4), warp tile 64x32,
// mma.sync.m16n8k8 tf32. Conflict-free fragment LDS via pitches 36 / 136.
// ---------------------------------------------------------------------------
#define APITCH 36
#define BPITCH 136

template<int MODE>
__global__ void __launch_bounds__(256)
sgemm_tf32_kernel(const float* __restrict__ A_in,
                  const float* __restrict__ W,
                  const float* __restrict__ bias,
                  float* __restrict__ C,
                  int M, int N, int K)
{
    const int BM = 128, BN = 128, BK = 32;
    extern __shared__ float sh[];
    float* As = sh;                     // [BM][APITCH]  (m-major, k inner)
    float* Bs = sh + BM * APITCH;       // [BK][BPITCH]  (k-major, n inner)

    const float* A = (MODE == 1) ? g_ao : A_in;

    const int tid    = threadIdx.x;
    const int warp   = tid >> 5;
    const int lane   = tid & 31;
    const int g      = lane >> 2;       // group 0..7
    const int tig    = lane & 3;        // 0..3
    const int warp_m = (warp >> 2) * 64;
    const int warp_n = (warp & 3) * 32;
    const int brow   = blockIdx.y * BM;
    const int bcol   = blockIdx.x * BN;

    // global-load coordinates
    const int ar = tid >> 3;            // 0..31 (A row step base)
    const int ac = (tid & 7) * 4;       // A col (k)
    const int br = tid >> 5;            // 0..7  (B row step base)
    const int bc = (tid & 31) * 4;      // B col (n)

    float acc[4][4][4];
    #pragma unroll
    for (int i = 0; i < 4; i++)
        #pragma unroll
        for (int j = 0; j < 4; j++)
            #pragma unroll
            for (int r = 0; r < 4; r++) acc[i][j][r] = 0.f;

    for (int k0 = 0; k0 < K; k0 += BK) {
        // load A tile 128x32 (4 float4 per thread), transposed convert to tf32
        #pragma unroll
        for (int i = 0; i < 4; i++) {
            const int r = i * 32 + ar;
            float4 v = *(const float4*)(A + (size_t)(brow + r) * K + k0 + ac);
            float* d = As + r * APITCH + ac;
            d[0] = f2tf32(v.x); d[1] = f2tf32(v.y);
            d[2] = f2tf32(v.z); d[3] = f2tf32(v.w);
        }
        // load B tile 32x128
        #pragma unroll
        for (int i = 0; i < 4; i++) {
            const int r = i * 8 + br;
            float4 v = *(const float4*)(W + (size_t)(k0 + r) * N + bcol + bc);
            float* d = Bs + r * BPITCH + bc;
            d[0] = f2tf32(v.x); d[1] = f2tf32(v.y);
            d[2] = f2tf32(v.z); d[3] = f2tf32(v.w);
        }
        __syncthreads();

        #pragma unroll
        for (int ks = 0; ks < 4; ks++) {
            const int kb = ks * 8;
            float afrag[4][4];
            #pragma unroll
            for (int mt = 0; mt < 4; mt++) {
                const int m = warp_m + mt * 16;
                afrag[mt][0] = As[(m + g)     * APITCH + kb + tig];
                afrag[mt][1] = As[(m + g + 8) * APITCH + kb + tig];
                afrag[mt][2] = As[(m + g)     * APITCH + kb + tig + 4];
                afrag[mt][3] = As[(m + g + 8) * APITCH + kb + tig + 4];
            }
            float bfrag[4][2];
            #pragma unroll
            for (int nt = 0; nt < 4; nt++) {
                const int n = warp_n + nt * 8;
                bfrag[nt][0] = Bs[(kb + tig)     * BPITCH + n + g];
                bfrag[nt][1] = Bs[(kb + tig + 4) * BPITCH + n + g];
            }
            #pragma unroll
            for (int mt = 0; mt < 4; mt++)
                #pragma unroll
                for (int nt = 0; nt < 4; nt++)
                    mma_tf32(acc[mt][nt], afrag[mt], bfrag[nt]);
        }
        __syncthreads();
    }

    // epilogue: each thread owns 4x4 tiles x 4 elements
    #pragma unroll
    for (int mt = 0; mt < 4; mt++) {
        #pragma unroll
        for (int nt = 0; nt < 4; nt++) {
            const int row0 = brow + warp_m + mt * 16 + g;
            const int col0 = bcol + warp_n + nt * 8 + tig * 2;
            #pragma unroll
            for (int r = 0; r < 4; r++) {
                const int m = row0 + (r >> 1) * 8;
                const int n = col0 + (r & 1);
                const float v = acc[mt][nt][r] + bias[n];
                if (MODE == 0) {
                    const int which = n >> 10;          // 0=q,1=k,2=v
                    const int e = n & (Ee - 1);
                    const int h = e >> 6;
                    const int d = e & (Dd - 1);
                    const int b = m >> 11;
                    const int s = m & (Ss - 1);
                    const size_t idx = (((size_t)(b * Hh + h)) * Ss + s) * Dd + d;
                    float* dst = (which == 0) ? g_q : ((which == 1) ? g_k : g_v);
                    dst[idx] = v;
                } else {
                    C[(size_t)m * N + n] = v;
                }
            }
        }
    }
}

// ---------------------------------------------------------------------------
// Flash attention, fp32 (unchanged from passing round-1 kernel).
// ---------------------------------------------------------------------------
__global__ void __launch_bounds__(256)
flash_attn_kernel(const int* __restrict__ amask)
{
    const int qt = blockIdx.x;
    const int h  = blockIdx.y;
    const int b  = blockIdx.z;

    extern __shared__ float sh[];
    float* Qs = sh;
    float* Ks = Qs + 64 * PITCH;
    float* Vs = Ks + 64 * PITCH;
    float* Ps = Vs + 64 * PITCH;
    __shared__ int mk[64];

    const int tid = threadIdx.x;
    const int ty  = tid >> 4;
    const int tx  = tid & 15;
    const float scale = 0.125f;

    const float* qptr  = g_q + (((size_t)(b * Hh + h)) * Ss + qt * 64) * Dd;
    const float* kbase = g_k + ((size_t)(b * Hh + h)) * Ss * Dd;
    const float* vbase = g_v + ((size_t)(b * Hh + h)) * Ss * Dd;

    for (int t = tid; t < 64 * 16; t += 256) {
        const int r  = t >> 4;
        const int c4 = (t & 15) * 4;
        float4 v = *(const float4*)(qptr + r * 64 + c4);
        Qs[r * PITCH + c4 + 0] = v.x;
        Qs[r * PITCH + c4 + 1] = v.y;
        Qs[r * PITCH + c4 + 2] = v.z;
        Qs[r * PITCH + c4 + 3] = v.w;
    }

    float m_i[4], l_i[4], o[4][4];
    #pragma unroll
    for (int i = 0; i < 4; i++) {
        m_i[i] = -INFINITY; l_i[i] = 0.f;
        #pragma unroll
        for (int j = 0; j < 4; j++) o[i][j] = 0.f;
    }

    for (int jt = 0; jt <= qt; jt++) {
        __syncthreads();
        for (int t = tid; t < 64 * 16; t += 256) {
            const int r  = t >> 4;
            const int c4 = (t & 15) * 4;
            float4 kv = *(const float4*)(kbase + (size_t)(jt * 64 + r) * 64 + c4);
            Ks[r * PITCH + c4 + 0] = kv.x; Ks[r * PITCH + c4 + 1] = kv.y;
            Ks[r * PITCH + c4 + 2] = kv.z; Ks[r * PITCH + c4 + 3] = kv.w;
            float4 vv = *(const float4*)(vbase + (size_t)(jt * 64 + r) * 64 + c4);
            Vs[r * PITCH + c4 + 0] = vv.x; Vs[r * PITCH + c4 + 1] = vv.y;
            Vs[r * PITCH + c4 + 2] = vv.z; Vs[r * PITCH + c4 + 3] = vv.w;
        }
        if (tid < 64) mk[tid] = amask[b * Ss + jt * 64 + tid];
        __syncthreads();

        float s[4][4];
        #pragma unroll
        for (int i = 0; i < 4; i++)
            #pragma unroll
            for (int j = 0; j < 4; j++) s[i][j] = 0.f;

        #pragma unroll 8
        for (int d = 0; d < 64; d++) {
            float qv[4], kv[4];
            #pragma unroll
            for (int i = 0; i < 4; i++) qv[i] = Qs[(ty * 4 + i) * PITCH + d];
            #pragma unroll
            for (int j = 0; j < 4; j++) kv[j] = Ks[(tx * 4 + j) * PITCH + d];
            #pragma unroll
            for (int i = 0; i < 4; i++)
                #pragma unroll
                for (int j = 0; j < 4; j++)
                    s[i][j] += qv[i] * kv[j];
        }

        const bool diag = (jt == qt);
        #pragma unroll
        for (int i = 0; i < 4; i++) {
            const int r = ty * 4 + i;
            #pragma unroll
            for (int j = 0; j < 4; j++) {
                const int c = tx * 4 + j;
                const bool ok = (mk[c] != 0) && (!diag || c <= r);
                s[i][j] = ok ? s[i][j] * scale : -INFINITY;
            }
        }

        #pragma unroll
        for (int i = 0; i < 4; i++) {
            float mx = fmaxf(fmaxf(s[i][0], s[i][1]), fmaxf(s[i][2], s[i][3]));
            #pragma unroll
            for (int off = 1; off < 16; off <<= 1)
                mx = fmaxf(mx, __shfl_xor_sync(0xffffffffu, mx, off));
            const float mnew  = fmaxf(m_i[i], mx);
            const float alpha = __expf(m_i[i] - mnew);
            float rsum = 0.f;
            #pragma unroll
            for (int j = 0; j < 4; j++) {
                s[i][j] = __expf(s[i][j] - mnew);
                rsum += s[i][j];
            }
            #pragma unroll
            for (int off = 1; off < 16; off <<= 1)
                rsum += __shfl_xor_sync(0xffffffffu, rsum, off);
            l_i[i] = l_i[i] * alpha + rsum;
            m_i[i] = mnew;
            #pragma unroll
            for (int j = 0; j < 4; j++) o[i][j] *= alpha;
        }

        #pragma unroll
        for (int i = 0; i < 4; i++)
            #pragma unroll
            for (int j = 0; j < 4; j++)
                Ps[(ty * 4 + i) * PITCH + tx * 4 + j] = s[i][j];
        __syncthreads();

        #pragma unroll 8
        for (int k = 0; k < 64; k++) {
            float pv[4], vv[4];
            #pragma unroll
            for (int i = 0; i < 4; i++) pv[i] = Ps[(ty * 4 + i) * PITCH + k];
            #pragma unroll
            for (int j = 0; j < 4; j++) vv[j] = Vs[k * PITCH + tx * 4 + j];
            #pragma unroll
            for (int i = 0; i < 4; i++)
                #pragma unroll
                for (int j = 0; j < 4; j++)
                    o[i][j] += pv[i] * vv[j];
        }
    }

    #pragma unroll
    for (int i = 0; i < 4; i++) {
        const int r = ty * 4 + i;
        const float inv = 1.f / l_i[i];
        const size_t rowoff = ((size_t)b * Ss + qt * 64 + r) * Ee + h * Dd;
        #pragma unroll
        for (int j = 0; j < 4; j++)
            g_ao[rowoff + tx * 4 + j] = o[i][j] * inv;
    }
}

// ---------------------------------------------------------------------------
extern "C" void kernel_launch(void* const* d_in, const int* in_sizes, int n_in,
                              void* d_out, int out_size)
{
    const float* x     = (const float*)d_in[0];
    const int*   amask = (const int*)  d_in[1];
    const float* Wqkv  = (const float*)d_in[2];
    const float* bqkv  = (const float*)d_in[3];
    const float* Wproj = (const float*)d_in[4];
    const float* bproj = (const float*)d_in[5];
    float* out = (float*)d_out;

    const int gemm_smem = (128 * APITCH + 32 * BPITCH) * sizeof(float); // ~35.8KB

    // 1) QKV GEMM (tf32 tensor cores): [8192,1024]@[1024,3072], scatter to BHSD
    {
        cudaFuncSetAttribute(sgemm_tf32_kernel<0>,
                             cudaFuncAttributeMaxDynamicSharedMemorySize, gemm_smem);
        dim3 grid(3 * Ee / 128, M1 / 128);   // 24 x 64
        sgemm_tf32_kernel<0><<<grid, 256, gemm_smem>>>(x, Wqkv, bqkv, nullptr,
                                                       M1, 3 * Ee, Ee);
    }

    // 2) Flash attention (fp32)
    {
        const size_t shbytes = (size_t)4 * 64 * PITCH * sizeof(float);
        cudaFuncSetAttribute(flash_attn_kernel,
                             cudaFuncAttributeMaxDynamicSharedMemorySize,
                             (int)shbytes);
        dim3 grid(Ss / 64, Hh, Bb);
        flash_attn_kernel<<<grid, 256, shbytes>>>(amask);
    }

    // 3) Projection GEMM (tf32 tensor cores): [8192,1024]@[1024,1024] -> out
    {
        cudaFuncSetAttribute(sgemm_tf32_kernel<1>,
                             cudaFuncAttributeMaxDynamicSharedMemorySize, gemm_smem);
        dim3 grid(Ee / 128, M1 / 128);       // 8 x 64
        sgemm_tf32_kernel<1><<<grid, 256, gemm_smem>>>(nullptr, Wproj, bproj, out,
                                                       M1, Ee, Ee);
    }
}

// round 3
// speedup vs baseline: 3.5102x; 1.9131x over previous
#include <cuda_runtime.h>
#include <math.h>
#include <stdint.h>

#define Bb 4
#define Ss 2048
#define Ee 1024
#define Hh 16
#define Dd 64
#define M1 (Bb*Ss)     // 8192

// Scratch (allocation-free: device globals)
__device__ float g_q[(size_t)Bb*Hh*Ss*Dd];   // [B,H,S,D]
__device__ float g_k[(size_t)Bb*Hh*Ss*Dd];
__device__ float g_v[(size_t)Bb*Hh*Ss*Dd];
__device__ float g_ao[(size_t)Bb*Ss*Ee];     // attention output [B,S,E]

__device__ __forceinline__ float f2tf32(float x) {
    uint32_t u;
    asm("cvt.rna.tf32.f32 %0, %1;" : "=r"(u) : "f"(x));
    return __uint_as_float(u);
}

__device__ __forceinline__ void mma_tf32(float* d, const float* a, const float* b) {
    asm volatile(
        "mma.sync.aligned.m16n8k8.row.col.f32.tf32.tf32.f32 "
        "{%0,%1,%2,%3}, {%4,%5,%6,%7}, {%8,%9}, {%0,%1,%2,%3};"
        : "+f"(d[0]), "+f"(d[1]), "+f"(d[2]), "+f"(d[3])
        : "r"(__float_as_uint(a[0])), "r"(__float_as_uint(a[1])),
          "r"(__float_as_uint(a[2])), "r"(__float_as_uint(a[3])),
          "r"(__float_as_uint(b[0])), "r"(__float_as_uint(b[1])));
}

// ---------------------------------------------------------------------------
// TF32 tensor-core GEMM (unchanged from round 2 — it passed at 391us)
// ---------------------------------------------------------------------------
#define APITCH 36
#define BPITCH 136

template<int MODE>
__global__ void __launch_bounds__(256)
sgemm_tf32_kernel(const float* __restrict__ A_in,
                  const float* __restrict__ W,
                  const float* __restrict__ bias,
                  float* __restrict__ C,
                  int M, int N, int K)
{
    const int BM = 128, BN = 128, BK = 32;
    extern __shared__ float sh[];
    float* As = sh;                     // [BM][APITCH]
    float* Bs = sh + BM * APITCH;       // [BK][BPITCH]

    const float* A = (MODE == 1) ? g_ao : A_in;

    const int tid    = threadIdx.x;
    const int warp   = tid >> 5;
    const int lane   = tid & 31;
    const int g      = lane >> 2;
    const int tig    = lane & 3;
    const int warp_m = (warp >> 2) * 64;
    const int warp_n = (warp & 3) * 32;
    const int brow   = blockIdx.y * BM;
    const int bcol   = blockIdx.x * BN;

    const int ar = tid >> 3;
    const int ac = (tid & 7) * 4;
    const int br = tid >> 5;
    const int bc = (tid & 31) * 4;

    float acc[4][4][4];
    #pragma unroll
    for (int i = 0; i < 4; i++)
        #pragma unroll
        for (int j = 0; j < 4; j++)
            #pragma unroll
            for (int r = 0; r < 4; r++) acc[i][j][r] = 0.f;

    for (int k0 = 0; k0 < K; k0 += BK) {
        #pragma unroll
        for (int i = 0; i < 4; i++) {
            const int r = i * 32 + ar;
            float4 v = *(const float4*)(A + (size_t)(brow + r) * K + k0 + ac);
            float* d = As + r * APITCH + ac;
            d[0] = f2tf32(v.x); d[1] = f2tf32(v.y);
            d[2] = f2tf32(v.z); d[3] = f2tf32(v.w);
        }
        #pragma unroll
        for (int i = 0; i < 4; i++) {
            const int r = i * 8 + br;
            float4 v = *(const float4*)(W + (size_t)(k0 + r) * N + bcol + bc);
            float* d = Bs + r * BPITCH + bc;
            d[0] = f2tf32(v.x); d[1] = f2tf32(v.y);
            d[2] = f2tf32(v.z); d[3] = f2tf32(v.w);
        }
        __syncthreads();

        #pragma unroll
        for (int ks = 0; ks < 4; ks++) {
            const int kb = ks * 8;
            float afrag[4][4];
            #pragma unroll
            for (int mt = 0; mt < 4; mt++) {
                const int m = warp_m + mt * 16;
                afrag[mt][0] = As[(m + g)     * APITCH + kb + tig];
                afrag[mt][1] = As[(m + g + 8) * APITCH + kb + tig];
                afrag[mt][2] = As[(m + g)     * APITCH + kb + tig + 4];
                afrag[mt][3] = As[(m + g + 8) * APITCH + kb + tig + 4];
            }
            float bfrag[4][2];
            #pragma unroll
            for (int nt = 0; nt < 4; nt++) {
                const int n = warp_n + nt * 8;
                bfrag[nt][0] = Bs[(kb + tig)     * BPITCH + n + g];
                bfrag[nt][1] = Bs[(kb + tig + 4) * BPITCH + n + g];
            }
            #pragma unroll
            for (int mt = 0; mt < 4; mt++)
                #pragma unroll
                for (int nt = 0; nt < 4; nt++)
                    mma_tf32(acc[mt][nt], afrag[mt], bfrag[nt]);
        }
        __syncthreads();
    }

    #pragma unroll
    for (int mt = 0; mt < 4; mt++) {
        #pragma unroll
        for (int nt = 0; nt < 4; nt++) {
            const int row0 = brow + warp_m + mt * 16 + g;
            const int col0 = bcol + warp_n + nt * 8 + tig * 2;
            #pragma unroll
            for (int r = 0; r < 4; r++) {
                const int m = row0 + (r >> 1) * 8;
                const int n = col0 + (r & 1);
                const float v = acc[mt][nt][r] + bias[n];
                if (MODE == 0) {
                    const int which = n >> 10;
                    const int e = n & (Ee - 1);
                    const int h = e >> 6;
                    const int d = e & (Dd - 1);
                    const int b = m >> 11;
                    const int s = m & (Ss - 1);
                    const size_t idx = (((size_t)(b * Hh + h)) * Ss + s) * Dd + d;
                    float* dst = (which == 0) ? g_q : ((which == 1) ? g_k : g_v);
                    dst[idx] = v;
                } else {
                    C[(size_t)m * N + n] = v;
                }
            }
        }
    }
}

// ---------------------------------------------------------------------------
// Flash attention on tensor cores (tf32 mma for QK^T and PV, fp32 softmax).
// 128 threads = 4 warps; warp w owns rows [w*16, w*16+16) of the 64-row tile.
// Smem pitches: 68 for Q/K/P (bank = 4g+tig, conflict-free),
//               72 for V    (bank = 8*tig+g, conflict-free).
// ---------------------------------------------------------------------------
#define QP 68
#define VP 72

__global__ void __launch_bounds__(128)
flash_mma_kernel(const int* __restrict__ amask)
{
    const int qt = (int)gridDim.x - 1 - (int)blockIdx.x;  // long blocks first
    const int h  = blockIdx.y;
    const int b  = blockIdx.z;

    extern __shared__ float sh[];
    float* Qs = sh;                    // [64][QP] tf32
    float* Ks = Qs + 64 * QP;          // [64][QP] tf32 (key-major, d inner)
    float* Ps = Ks + 64 * QP;          // [64][QP] tf32
    float* Vs = Ps + 64 * QP;          // [64][VP] tf32 (key-major, d inner)
    int*   mk = (int*)(Vs + 64 * VP);  // [64]

    const int tid  = threadIdx.x;
    const int warp = tid >> 5;
    const int lane = tid & 31;
    const int g    = lane >> 2;        // 0..7
    const int tig  = lane & 3;         // 0..3
    const float scale = 0.125f;

    const float* qptr  = g_q + (((size_t)(b * Hh + h)) * Ss + qt * 64) * Dd;
    const float* kbase = g_k + ((size_t)(b * Hh + h)) * Ss * Dd;
    const float* vbase = g_v + ((size_t)(b * Hh + h)) * Ss * Dd;

    // Load Q tile (tf32 convert)
    for (int t = tid; t < 64 * 16; t += 128) {
        const int r  = t >> 4;
        const int c4 = (t & 15) * 4;
        float4 v = *(const float4*)(qptr + r * 64 + c4);
        float* d = Qs + r * QP + c4;
        d[0] = f2tf32(v.x); d[1] = f2tf32(v.y);
        d[2] = f2tf32(v.z); d[3] = f2tf32(v.w);
    }

    const int r0 = warp * 16 + g;      // this thread's row (within 64)
    const int r1 = r0 + 8;

    float o[8][4];
    #pragma unroll
    for (int nt = 0; nt < 8; nt++)
        #pragma unroll
        for (int c = 0; c < 4; c++) o[nt][c] = 0.f;
    float m0 = -INFINITY, m1 = -INFINITY, l0 = 0.f, l1 = 0.f;

    for (int jt = 0; jt <= qt; jt++) {
        __syncthreads();
        // Load K, V tiles (tf32 convert) + mask slice
        for (int t = tid; t < 64 * 16; t += 128) {
            const int r  = t >> 4;
            const int c4 = (t & 15) * 4;
            float4 kv = *(const float4*)(kbase + (size_t)(jt * 64 + r) * 64 + c4);
            float* dk = Ks + r * QP + c4;
            dk[0] = f2tf32(kv.x); dk[1] = f2tf32(kv.y);
            dk[2] = f2tf32(kv.z); dk[3] = f2tf32(kv.w);
            float4 vv = *(const float4*)(vbase + (size_t)(jt * 64 + r) * 64 + c4);
            float* dv = Vs + r * VP + c4;
            dv[0] = f2tf32(vv.x); dv[1] = f2tf32(vv.y);
            dv[2] = f2tf32(vv.z); dv[3] = f2tf32(vv.w);
        }
        if (tid < 64) mk[tid] = amask[b * Ss + jt * 64 + tid];
        __syncthreads();

        // ---- S = Q K^T (tensor cores) ----
        float s[8][4];
        #pragma unroll
        for (int nt = 0; nt < 8; nt++)
            #pragma unroll
            for (int c = 0; c < 4; c++) s[nt][c] = 0.f;

        #pragma unroll
        for (int kb8 = 0; kb8 < 8; kb8++) {
            const int kb = kb8 * 8;
            float a[4];
            a[0] = Qs[r0 * QP + kb + tig];
            a[1] = Qs[r1 * QP + kb + tig];
            a[2] = Qs[r0 * QP + kb + tig + 4];
            a[3] = Qs[r1 * QP + kb + tig + 4];
            #pragma unroll
            for (int nt = 0; nt < 8; nt++) {
                float bf[2];
                bf[0] = Ks[(nt * 8 + g) * QP + kb + tig];
                bf[1] = Ks[(nt * 8 + g) * QP + kb + tig + 4];
                mma_tf32(s[nt], a, bf);
            }
        }

        // ---- mask + scale ----
        const bool diag = (jt == qt);
        #pragma unroll
        for (int nt = 0; nt < 8; nt++) {
            #pragma unroll
            for (int c = 0; c < 4; c++) {
                const int col = nt * 8 + tig * 2 + (c & 1);
                const int row = (c < 2) ? r0 : r1;
                const bool ok = (mk[col] != 0) && (!diag || col <= row);
                s[nt][c] = ok ? s[nt][c] * scale : -INFINITY;
            }
        }

        // ---- online softmax (rows r0, r1; reduce over 4 tig lanes) ----
        float mx0 = -INFINITY, mx1 = -INFINITY;
        #pragma unroll
        for (int nt = 0; nt < 8; nt++) {
            mx0 = fmaxf(mx0, fmaxf(s[nt][0], s[nt][1]));
            mx1 = fmaxf(mx1, fmaxf(s[nt][2], s[nt][3]));
        }
        #pragma unroll
        for (int off = 1; off < 4; off <<= 1) {
            mx0 = fmaxf(mx0, __shfl_xor_sync(0xffffffffu, mx0, off));
            mx1 = fmaxf(mx1, __shfl_xor_sync(0xffffffffu, mx1, off));
        }
        const float mn0 = fmaxf(m0, mx0);
        const float mn1 = fmaxf(m1, mx1);
        const float al0 = __expf(m0 - mn0);
        const float al1 = __expf(m1 - mn1);

        float sum0 = 0.f, sum1 = 0.f;
        #pragma unroll
        for (int nt = 0; nt < 8; nt++) {
            s[nt][0] = __expf(s[nt][0] - mn0); sum0 += s[nt][0];
            s[nt][1] = __expf(s[nt][1] - mn0); sum0 += s[nt][1];
            s[nt][2] = __expf(s[nt][2] - mn1); sum1 += s[nt][2];
            s[nt][3] = __expf(s[nt][3] - mn1); sum1 += s[nt][3];
        }
        #pragma unroll
        for (int off = 1; off < 4; off <<= 1) {
            sum0 += __shfl_xor_sync(0xffffffffu, sum0, off);
            sum1 += __shfl_xor_sync(0xffffffffu, sum1, off);
        }
        l0 = l0 * al0 + sum0;  m0 = mn0;
        l1 = l1 * al1 + sum1;  m1 = mn1;

        #pragma unroll
        for (int nt = 0; nt < 8; nt++) {
            o[nt][0] *= al0; o[nt][1] *= al0;
            o[nt][2] *= al1; o[nt][3] *= al1;
        }

        // ---- stage P to smem (tf32), warp-private rows ----
        #pragma unroll
        for (int nt = 0; nt < 8; nt++) {
            const int cc = nt * 8 + tig * 2;
            Ps[r0 * QP + cc]     = f2tf32(s[nt][0]);
            Ps[r0 * QP + cc + 1] = f2tf32(s[nt][1]);
            Ps[r1 * QP + cc]     = f2tf32(s[nt][2]);
            Ps[r1 * QP + cc + 1] = f2tf32(s[nt][3]);
        }
        __syncwarp();

        // ---- O += P V (tensor cores) ----
        #pragma unroll
        for (int kb8 = 0; kb8 < 8; kb8++) {
            const int kb = kb8 * 8;
            float a[4];
            a[0] = Ps[r0 * QP + kb + tig];
            a[1] = Ps[r1 * QP + kb + tig];
            a[2] = Ps[r0 * QP + kb + tig + 4];
            a[3] = Ps[r1 * QP + kb + tig + 4];
            #pragma unroll
            for (int nt = 0; nt < 8; nt++) {
                float bf[2];
                bf[0] = Vs[(kb + tig)     * VP + nt * 8 + g];
                bf[1] = Vs[(kb + tig + 4) * VP + nt * 8 + g];
                mma_tf32(o[nt], a, bf);
            }
        }
        __syncwarp();
    }

    // ---- normalize + write out [B,S,E] at column offset h*D ----
    const float inv0 = 1.f / l0;
    const float inv1 = 1.f / l1;
    const size_t row0off = ((size_t)b * Ss + qt * 64 + r0) * Ee + h * Dd;
    const size_t row1off = ((size_t)b * Ss + qt * 64 + r1) * Ee + h * Dd;
    #pragma unroll
    for (int nt = 0; nt < 8; nt++) {
        const int cc = nt * 8 + tig * 2;
        g_ao[row0off + cc]     = o[nt][0] * inv0;
        g_ao[row0off + cc + 1] = o[nt][1] * inv0;
        g_ao[row1off + cc]     = o[nt][2] * inv1;
        g_ao[row1off + cc + 1] = o[nt][3] * inv1;
    }
}

// ---------------------------------------------------------------------------
extern "C" void kernel_launch(void* const* d_in, const int* in_sizes, int n_in,
                              void* d_out, int out_size)
{
    const float* x     = (const float*)d_in[0];
    const int*   amask = (const int*)  d_in[1];
    const float* Wqkv  = (const float*)d_in[2];
    const float* bqkv  = (const float*)d_in[3];
    const float* Wproj = (const float*)d_in[4];
    const float* bproj = (const float*)d_in[5];
    float* out = (float*)d_out;

    const int gemm_smem = (128 * APITCH + 32 * BPITCH) * sizeof(float);

    // 1) QKV GEMM (tf32): [8192,1024]@[1024,3072] -> scatter BHSD
    {
        cudaFuncSetAttribute(sgemm_tf32_kernel<0>,
                             cudaFuncAttributeMaxDynamicSharedMemorySize, gemm_smem);
        dim3 grid(3 * Ee / 128, M1 / 128);
        sgemm_tf32_kernel<0><<<grid, 256, gemm_smem>>>(x, Wqkv, bqkv, nullptr,
                                                       M1, 3 * Ee, Ee);
    }

    // 2) Flash attention (tf32 tensor cores)
    {
        const int shbytes = (3 * 64 * QP + 64 * VP) * sizeof(float) + 64 * sizeof(int);
        cudaFuncSetAttribute(flash_mma_kernel,
                             cudaFuncAttributeMaxDynamicSharedMemorySize, shbytes);
        dim3 grid(Ss / 64, Hh, Bb);
        flash_mma_kernel<<<grid, 128, shbytes>>>(amask);
    }

    // 3) Projection GEMM (tf32): [8192,1024]@[1024,1024] -> out
    {
        cudaFuncSetAttribute(sgemm_tf32_kernel<1>,
                             cudaFuncAttributeMaxDynamicSharedMemorySize, gemm_smem);
        dim3 grid(Ee / 128, M1 / 128);
        sgemm_tf32_kernel<1><<<grid, 256, gemm_smem>>>(nullptr, Wproj, bproj, out,
                                                       M1, Ee, Ee);
    }
}